// round 7
// baseline (speedup 1.0000x reference)
#include <cuda_runtime.h>
#include <stdint.h>

#define M_DIM 2048   // 8*256
#define N_DIM 1024   // out_features
#define K_DIM 1024   // in_features

// Scratch (device globals; no allocation allowed)
__device__ float g_xf[M_DIM * K_DIM];  // decoded x  [M,K]
__device__ float g_wf[N_DIM * K_DIM];  // decoded w  [N,K]
__device__ float g_y [M_DIM * N_DIM]; // fp32 matmul result

// ---------------------------------------------------------------------------
// Decode FP8-E4M3 bit pulses -> fp32 (exact).
// ---------------------------------------------------------------------------
__global__ void __launch_bounds__(256) decode_kernel(
    const float4* __restrict__ p, float* __restrict__ out, int n)
{
    int i = blockIdx.x * blockDim.x + threadIdx.x;
    if (i >= n) return;
    float4 a = p[2 * i];
    float4 b = p[2 * i + 1];
    int s  = a.x > 0.5f;
    int ev = ((a.y > 0.5f) << 3) | ((a.z > 0.5f) << 2) |
             ((a.w > 0.5f) << 1) |  (b.x > 0.5f);
    int mv = ((b.y > 0.5f) << 2) | ((b.z > 0.5f) << 1) | (b.w > 0.5f);
    float frac = (float)mv * 0.125f;
    float mag;
    if (ev == 0) {
        mag = frac * 0.015625f;                     // frac * 2^-6 (exact)
    } else {
        float scale = __uint_as_float((unsigned)(ev + 120) << 23);  // 2^(ev-7)
        mag = (1.0f + frac) * scale;                // exact
    }
    out[i] = s ? -mag : mag;
}

// ---------------------------------------------------------------------------
// fp32 GEMM reproducing the reference accumulation order (validated R6 probe):
//   split-K = 2: s0 = flat ascending chain k in [0,512),
//                s1 = flat ascending chain k in [512,1024),
//                y  = s0 + s1   (single fp32 add)
// 128x128 tile, BK=16, 256 threads, 8x8 micro-tile per thread.
// ---------------------------------------------------------------------------
#define BM 128
#define BN 128
#define BK 16
#define NTILES (K_DIM / BK)   // 64; fold boundary after tile 31
#define LDS_PAD 4

__global__ void __launch_bounds__(256) gemm_kernel()
{
    __shared__ float As[BK][BM + LDS_PAD];
    __shared__ float Bs[BK][BN + LDS_PAD];

    const int tid = threadIdx.x;
    const int tx  = tid & 15;
    const int ty  = tid >> 4;
    const int m0  = blockIdx.y * BM;
    const int n0  = blockIdx.x * BN;

    float cur[8][8];   // running chain for current K half
    float tot[8][8];   // folded total
#pragma unroll
    for (int i = 0; i < 8; i++)
#pragma unroll
        for (int j = 0; j < 8; j++) { cur[i][j] = 0.0f; tot[i][j] = 0.0f; }

    for (int kt = 0; kt < NTILES; kt++) {
        const int k0 = kt * BK;
#pragma unroll
        for (int it = 0; it < 2; it++) {
            int lin = tid + it * 256;
            int row = lin >> 2;
            int cg  = lin & 3;
            float4 va = *(const float4*)&g_xf[(size_t)(m0 + row) * K_DIM + k0 + cg * 4];
            As[cg * 4 + 0][row] = va.x;
            As[cg * 4 + 1][row] = va.y;
            As[cg * 4 + 2][row] = va.z;
            As[cg * 4 + 3][row] = va.w;
            float4 vb = *(const float4*)&g_wf[(size_t)(n0 + row) * K_DIM + k0 + cg * 4];
            Bs[cg * 4 + 0][row] = vb.x;
            Bs[cg * 4 + 1][row] = vb.y;
            Bs[cg * 4 + 2][row] = vb.z;
            Bs[cg * 4 + 3][row] = vb.w;
        }
        __syncthreads();

#pragma unroll
        for (int kk = 0; kk < BK; kk++) {
            float a[8], b[8];
            float4 a0 = *(const float4*)&As[kk][ty * 8];
            float4 a1 = *(const float4*)&As[kk][ty * 8 + 4];
            float4 b0 = *(const float4*)&Bs[kk][tx * 8];
            float4 b1 = *(const float4*)&Bs[kk][tx * 8 + 4];
            a[0]=a0.x; a[1]=a0.y; a[2]=a0.z; a[3]=a0.w;
            a[4]=a1.x; a[5]=a1.y; a[6]=a1.z; a[7]=a1.w;
            b[0]=b0.x; b[1]=b0.y; b[2]=b0.z; b[3]=b0.w;
            b[4]=b1.x; b[5]=b1.y; b[6]=b1.z; b[7]=b1.w;
#pragma unroll
            for (int i = 0; i < 8; i++)
#pragma unroll
                for (int j = 0; j < 8; j++)
                    cur[i][j] = fmaf(a[i], b[j], cur[i][j]);
        }
        __syncthreads();

        if (kt == 31) {            // end of first K half: assign
#pragma unroll
            for (int i = 0; i < 8; i++)
#pragma unroll
                for (int j = 0; j < 8; j++) { tot[i][j] = cur[i][j]; cur[i][j] = 0.0f; }
        }
    }

    // end of second K half: single fp32 add
#pragma unroll
    for (int i = 0; i < 8; i++) {
        size_t base = (size_t)(m0 + ty * 8 + i) * N_DIM + n0 + tx * 8;
        *(float4*)&g_y[base] = make_float4(
            tot[i][0] + cur[i][0], tot[i][1] + cur[i][1],
            tot[i][2] + cur[i][2], tot[i][3] + cur[i][3]);
        *(float4*)&g_y[base + 4] = make_float4(
            tot[i][4] + cur[i][4], tot[i][5] + cur[i][5],
            tot[i][6] + cur[i][6], tot[i][7] + cur[i][7]);
    }
}

// ---------------------------------------------------------------------------
// Encode fp32 -> 32 bit pulses (MSB/sign first). One thread per 4 bits.
// ---------------------------------------------------------------------------
__global__ void __launch_bounds__(256) encode_kernel(
    const float* __restrict__ y, float4* __restrict__ out, int n4)
{
    int i = blockIdx.x * blockDim.x + threadIdx.x;
    if (i >= n4) return;
    int e = i >> 3;
    int g = i & 7;
    unsigned bits = __float_as_uint(y[e]);
    int sh = 31 - g * 4;
    float4 o;
    o.x = (float)((bits >> sh)       & 1u);
    o.y = (float)((bits >> (sh - 1)) & 1u);
    o.z = (float)((bits >> (sh - 2)) & 1u);
    o.w = (float)((bits >> (sh - 3)) & 1u);
    out[i] = o;
}

// ---------------------------------------------------------------------------
extern "C" void kernel_launch(void* const* d_in, const int* in_sizes, int n_in,
                              void* d_out, int out_size)
{
    const float4* x = (const float4*)d_in[0];   // [8,256,1024,8]
    const float4* w = (const float4*)d_in[1];   // [1024,1024,8]

    float* xf; cudaGetSymbolAddress((void**)&xf, g_xf);
    float* wf; cudaGetSymbolAddress((void**)&wf, g_wf);
    float* y;  cudaGetSymbolAddress((void**)&y,  g_y);

    const int nx = M_DIM * K_DIM;
    const int nw = N_DIM * K_DIM;

    decode_kernel<<<(nx + 255) / 256, 256>>>(x, xf, nx);
    decode_kernel<<<(nw + 255) / 256, 256>>>(w, wf, nw);

    dim3 ggrid(N_DIM / BN, M_DIM / BM);   // (8, 16)
    gemm_kernel<<<ggrid, 256>>>();

    const int n4 = M_DIM * N_DIM * 8;
    encode_kernel<<<(n4 + 255) / 256, 256>>>(y, (float4*)d_out, n4);
}

// round 8
// speedup vs baseline: 1.1477x; 1.1477x over previous
#include <cuda_runtime.h>
#include <stdint.h>

#define M_DIM 2048   // 8*256
#define N_DIM 1024   // out_features
#define K_DIM 1024   // in_features
#define KHALF 512

// Scratch (device globals; no allocation allowed)
__device__ float g_xf[M_DIM * K_DIM];  // decoded x  [M,K]
__device__ float g_wf[N_DIM * K_DIM];  // decoded w  [N,K]
__device__ float g_y [M_DIM * N_DIM]; // fp32 matmul result

// ---------------------------------------------------------------------------
// Decode FP8-E4M3 bit pulses -> fp32 (exact).
// ---------------------------------------------------------------------------
__global__ void __launch_bounds__(256) decode_kernel(
    const float4* __restrict__ p, float* __restrict__ out, int n)
{
    int i = blockIdx.x * blockDim.x + threadIdx.x;
    if (i >= n) return;
    float4 a = p[2 * i];
    float4 b = p[2 * i + 1];
    int s  = a.x > 0.5f;
    int ev = ((a.y > 0.5f) << 3) | ((a.z > 0.5f) << 2) |
             ((a.w > 0.5f) << 1) |  (b.x > 0.5f);
    int mv = ((b.y > 0.5f) << 2) | ((b.z > 0.5f) << 1) | (b.w > 0.5f);
    float frac = (float)mv * 0.125f;
    float mag;
    if (ev == 0) {
        mag = frac * 0.015625f;                     // frac * 2^-6 (exact)
    } else {
        float scale = __uint_as_float((unsigned)(ev + 120) << 23);  // 2^(ev-7)
        mag = (1.0f + frac) * scale;                // exact
    }
    out[i] = s ? -mag : mag;
}

// ---------------------------------------------------------------------------
// fp32 GEMM, split-K=2 reference order, one half-K chain per kernel:
//   HALF=0: g_y  = chain over k in [0,512)
//   HALF=1: g_y += chain over k in [512,1024)   (single fp32 add)
// 128x128 tile, BK=16, 256 threads, 8x8 micro-tile, register double-buffer.
// ---------------------------------------------------------------------------
#define BM 128
#define BN 128
#define BK 16
#define NHT (KHALF / BK)   // 32 tiles per half
#define LDS_PAD 4

template<int HALF>
__global__ void __launch_bounds__(256) gemm_half_kernel()
{
    __shared__ float As[BK][BM + LDS_PAD];
    __shared__ float Bs[BK][BN + LDS_PAD];

    const int tid = threadIdx.x;
    const int tx  = tid & 15;
    const int ty  = tid >> 4;
    const int m0  = blockIdx.y * BM;
    const int n0  = blockIdx.x * BN;
    const int KOFF = HALF * KHALF;

    // per-thread load slots: lin = tid + it*256; row = lin>>2; cg = lin&3
    const int row0 = tid >> 2, row1 = (tid + 256) >> 2;
    const int cg0  = tid & 3,  cg1  = (tid + 256) & 3;
    const float* Axp0 = &g_xf[(size_t)(m0 + row0) * K_DIM + KOFF + cg0 * 4];
    const float* Axp1 = &g_xf[(size_t)(m0 + row1) * K_DIM + KOFF + cg1 * 4];
    const float* Bxp0 = &g_wf[(size_t)(n0 + row0) * K_DIM + KOFF + cg0 * 4];
    const float* Bxp1 = &g_wf[(size_t)(n0 + row1) * K_DIM + KOFF + cg1 * 4];

    float acc[8][8];
#pragma unroll
    for (int i = 0; i < 8; i++)
#pragma unroll
        for (int j = 0; j < 8; j++) acc[i][j] = 0.0f;

    // prologue: load tile 0 and store to smem
    float4 ra0 = *(const float4*)Axp0;
    float4 ra1 = *(const float4*)Axp1;
    float4 rb0 = *(const float4*)Bxp0;
    float4 rb1 = *(const float4*)Bxp1;
#pragma unroll
    for (int q = 0; q < 1; q++) { } // (keep structure flat)
    As[cg0*4+0][row0]=ra0.x; As[cg0*4+1][row0]=ra0.y; As[cg0*4+2][row0]=ra0.z; As[cg0*4+3][row0]=ra0.w;
    As[cg1*4+0][row1]=ra1.x; As[cg1*4+1][row1]=ra1.y; As[cg1*4+2][row1]=ra1.z; As[cg1*4+3][row1]=ra1.w;
    Bs[cg0*4+0][row0]=rb0.x; Bs[cg0*4+1][row0]=rb0.y; Bs[cg0*4+2][row0]=rb0.z; Bs[cg0*4+3][row0]=rb0.w;
    Bs[cg1*4+0][row1]=rb1.x; Bs[cg1*4+1][row1]=rb1.y; Bs[cg1*4+2][row1]=rb1.z; Bs[cg1*4+3][row1]=rb1.w;
    __syncthreads();

    for (int kt = 0; kt < NHT; kt++) {
        // prefetch next tile into registers (overlaps with compute below)
        if (kt + 1 < NHT) {
            const int koff = (kt + 1) * BK;
            ra0 = *(const float4*)(Axp0 + koff);
            ra1 = *(const float4*)(Axp1 + koff);
            rb0 = *(const float4*)(Bxp0 + koff);
            rb1 = *(const float4*)(Bxp1 + koff);
        }

#pragma unroll
        for (int kk = 0; kk < BK; kk++) {
            float a[8], b[8];
            float4 a0 = *(const float4*)&As[kk][ty * 8];
            float4 a1 = *(const float4*)&As[kk][ty * 8 + 4];
            float4 b0 = *(const float4*)&Bs[kk][tx * 8];
            float4 b1 = *(const float4*)&Bs[kk][tx * 8 + 4];
            a[0]=a0.x; a[1]=a0.y; a[2]=a0.z; a[3]=a0.w;
            a[4]=a1.x; a[5]=a1.y; a[6]=a1.z; a[7]=a1.w;
            b[0]=b0.x; b[1]=b0.y; b[2]=b0.z; b[3]=b0.w;
            b[4]=b1.x; b[5]=b1.y; b[6]=b1.z; b[7]=b1.w;
#pragma unroll
            for (int i = 0; i < 8; i++)
#pragma unroll
                for (int j = 0; j < 8; j++)
                    acc[i][j] = fmaf(a[i], b[j], acc[i][j]);
        }
        __syncthreads();

        if (kt + 1 < NHT) {
            As[cg0*4+0][row0]=ra0.x; As[cg0*4+1][row0]=ra0.y; As[cg0*4+2][row0]=ra0.z; As[cg0*4+3][row0]=ra0.w;
            As[cg1*4+0][row1]=ra1.x; As[cg1*4+1][row1]=ra1.y; As[cg1*4+2][row1]=ra1.z; As[cg1*4+3][row1]=ra1.w;
            Bs[cg0*4+0][row0]=rb0.x; Bs[cg0*4+1][row0]=rb0.y; Bs[cg0*4+2][row0]=rb0.z; Bs[cg0*4+3][row0]=rb0.w;
            Bs[cg1*4+0][row1]=rb1.x; Bs[cg1*4+1][row1]=rb1.y; Bs[cg1*4+2][row1]=rb1.z; Bs[cg1*4+3][row1]=rb1.w;
            __syncthreads();
        }
    }

#pragma unroll
    for (int i = 0; i < 8; i++) {
        size_t base = (size_t)(m0 + ty * 8 + i) * N_DIM + n0 + tx * 8;
        if (HALF == 0) {
            *(float4*)&g_y[base]     = make_float4(acc[i][0], acc[i][1], acc[i][2], acc[i][3]);
            *(float4*)&g_y[base + 4] = make_float4(acc[i][4], acc[i][5], acc[i][6], acc[i][7]);
        } else {
            float4 s0a = *(const float4*)&g_y[base];
            float4 s0b = *(const float4*)&g_y[base + 4];
            *(float4*)&g_y[base] = make_float4(
                s0a.x + acc[i][0], s0a.y + acc[i][1],
                s0a.z + acc[i][2], s0a.w + acc[i][3]);
            *(float4*)&g_y[base + 4] = make_float4(
                s0b.x + acc[i][4], s0b.y + acc[i][5],
                s0b.z + acc[i][6], s0b.w + acc[i][7]);
        }
    }
}

// ---------------------------------------------------------------------------
// Encode fp32 -> 32 bit pulses (MSB/sign first). One thread per 4 bits.
// Streaming stores: output is write-once, never re-read -> bypass L2 resident.
// ---------------------------------------------------------------------------
__global__ void __launch_bounds__(256) encode_kernel(
    const float* __restrict__ y, float4* __restrict__ out, int n4)
{
    int i = blockIdx.x * blockDim.x + threadIdx.x;
    if (i >= n4) return;
    int e = i >> 3;
    int g = i & 7;
    unsigned bits = __float_as_uint(__ldg(&y[e]));
    int sh = 31 - g * 4;
    float4 o;
    o.x = (float)((bits >> sh)       & 1u);
    o.y = (float)((bits >> (sh - 1)) & 1u);
    o.z = (float)((bits >> (sh - 2)) & 1u);
    o.w = (float)((bits >> (sh - 3)) & 1u);
    __stcs(&out[i], o);
}

// ---------------------------------------------------------------------------
extern "C" void kernel_launch(void* const* d_in, const int* in_sizes, int n_in,
                              void* d_out, int out_size)
{
    const float4* x = (const float4*)d_in[0];   // [8,256,1024,8]
    const float4* w = (const float4*)d_in[1];   // [1024,1024,8]

    float* xf; cudaGetSymbolAddress((void**)&xf, g_xf);
    float* wf; cudaGetSymbolAddress((void**)&wf, g_wf);
    float* y;  cudaGetSymbolAddress((void**)&y,  g_y);

    const int nx = M_DIM * K_DIM;
    const int nw = N_DIM * K_DIM;

    decode_kernel<<<(nx + 255) / 256, 256>>>(x, xf, nx);
    decode_kernel<<<(nw + 255) / 256, 256>>>(w, wf, nw);

    dim3 ggrid(N_DIM / BN, M_DIM / BM);   // (8, 16)
    gemm_half_kernel<0><<<ggrid, 256>>>();
    gemm_half_kernel<1><<<ggrid, 256>>>();

    const int n4 = M_DIM * N_DIM * 8;
    encode_kernel<<<(n4 + 255) / 256, 256>>>(y, (float4*)d_out, n4);
}

// round 9
// speedup vs baseline: 1.2350x; 1.0760x over previous
#include <cuda_runtime.h>
#include <stdint.h>

#define M_DIM 2048   // 8*256
#define N_DIM 1024   // out_features
#define K_DIM 1024   // in_features
#define KHALF 512

// Scratch (device globals; no allocation allowed)
// K-major (transposed) decoded operands:
__device__ float g_xf[K_DIM * M_DIM];  // xf_t[k][m]
__device__ float g_wf[K_DIM * N_DIM];  // wf_t[k][n]
__device__ float g_y0[M_DIM * N_DIM];  // s0 = chain k in [0,512)
__device__ float g_y1[M_DIM * N_DIM];  // s1 = chain k in [512,1024)

// ---------------------------------------------------------------------------
// Decode FP8-E4M3 bit pulses -> fp32 (exact), writing K-major transposed.
// Source: rows x 1024 elements, 8 pulses each. Dest: out[k*rows + m].
// 32x32 tile transpose through smem; reads and writes fully coalesced.
// ---------------------------------------------------------------------------
__device__ __forceinline__ float decode_one(const float4* p)
{
    float4 a = p[0];
    float4 b = p[1];
    int s  = a.x > 0.5f;
    int ev = ((a.y > 0.5f) << 3) | ((a.z > 0.5f) << 2) |
             ((a.w > 0.5f) << 1) |  (b.x > 0.5f);
    int mv = ((b.y > 0.5f) << 2) | ((b.z > 0.5f) << 1) | (b.w > 0.5f);
    float frac = (float)mv * 0.125f;
    float mag;
    if (ev == 0) {
        mag = frac * 0.015625f;                     // frac * 2^-6 (exact)
    } else {
        float scale = __uint_as_float((unsigned)(ev + 120) << 23);  // 2^(ev-7)
        mag = (1.0f + frac) * scale;                // exact
    }
    return s ? -mag : mag;
}

__global__ void __launch_bounds__(256) decode_t_kernel(
    const float4* __restrict__ p, float* __restrict__ out, int rows)
{
    __shared__ float tile[32][33];
    const int m0 = blockIdx.y * 32;
    const int k0 = blockIdx.x * 32;
    const int t  = threadIdx.x;

#pragma unroll
    for (int r = 0; r < 4; r++) {
        int lin = t + r * 256;          // 0..1023, m-major
        int mm  = lin >> 5;
        int kk  = lin & 31;
        tile[kk][mm] = decode_one(p + 2 * ((size_t)(m0 + mm) * K_DIM + k0 + kk));
    }
    __syncthreads();
#pragma unroll
    for (int r = 0; r < 4; r++) {
        int lin = t + r * 256;          // k-major
        int kk  = lin >> 5;
        int mm  = lin & 31;
        out[(size_t)(k0 + kk) * rows + m0 + mm] = tile[kk][mm];
    }
}

// ---------------------------------------------------------------------------
// fp32 GEMM, split-K=2 reference order; blockIdx.z selects K half.
// Half z computes flat ascending chain over its 512 k's into g_y{z}.
// 128x128 tile, BK=16, 256 threads, 8x8 micro-tile, cp.async double buffer.
// ---------------------------------------------------------------------------
#define BM 128
#define BN 128
#define BK 16
#define NHT (KHALF / BK)   // 32 tiles per half
#define PAD 4
#define SROW (BM + PAD)    // 132 floats; row stride 528B = 33*16 (16B aligned)

#define CP_ASYNC16(dst_u32, src_ptr) \
    asm volatile("cp.async.cg.shared.global [%0], [%1], 16;" \
                 :: "r"(dst_u32), "l"(src_ptr))
#define CP_COMMIT() asm volatile("cp.async.commit_group;")
#define CP_WAIT(n)  asm volatile("cp.async.wait_group %0;" :: "n"(n))

__device__ __forceinline__ uint32_t smem_u32(const void* p) {
    uint32_t a;
    asm("{ .reg .u64 t; cvta.to.shared.u64 t, %1; cvt.u32.u64 %0, t; }"
        : "=r"(a) : "l"(p));
    return a;
}

__global__ void __launch_bounds__(256, 2) gemm_kernel()
{
    __shared__ float As[2][BK][SROW];
    __shared__ float Bs[2][BK][SROW];

    const int tid = threadIdx.x;
    const int tx  = tid & 15;
    const int ty  = tid >> 4;
    const int m0  = blockIdx.y * BM;
    const int n0  = blockIdx.x * BN;
    const int KOFF = blockIdx.z * KHALF;
    float* yout = blockIdx.z ? g_y1 : g_y0;

    // load slots: chunk c in [0,512) per operand; kk = c>>5, pos = c&31
    const int kkA = tid >> 5,           posA = tid & 31;          // c = tid
    const int kkB = (tid + 256) >> 5,   posB = (tid + 256) & 31;  // c = tid+256
    const float* Asrc0 = &g_xf[(size_t)(KOFF + kkA) * M_DIM + m0 + posA * 4];
    const float* Asrc1 = &g_xf[(size_t)(KOFF + kkB) * M_DIM + m0 + posB * 4];
    const float* Bsrc0 = &g_wf[(size_t)(KOFF + kkA) * N_DIM + n0 + posA * 4];
    const float* Bsrc1 = &g_wf[(size_t)(KOFF + kkB) * N_DIM + n0 + posB * 4];
    const size_t stepA = (size_t)BK * M_DIM;   // advance one k-tile
    const size_t stepB = (size_t)BK * N_DIM;

    uint32_t dA0[2], dA1[2], dB0[2], dB1[2];
#pragma unroll
    for (int b = 0; b < 2; b++) {
        dA0[b] = smem_u32(&As[b][kkA][posA * 4]);
        dA1[b] = smem_u32(&As[b][kkB][posB * 4]);
        dB0[b] = smem_u32(&Bs[b][kkA][posA * 4]);
        dB1[b] = smem_u32(&Bs[b][kkB][posB * 4]);
    }

    float acc[8][8];
#pragma unroll
    for (int i = 0; i < 8; i++)
#pragma unroll
        for (int j = 0; j < 8; j++) acc[i][j] = 0.0f;

    // prologue: fill buffer 0
    CP_ASYNC16(dA0[0], Asrc0);
    CP_ASYNC16(dA1[0], Asrc1);
    CP_ASYNC16(dB0[0], Bsrc0);
    CP_ASYNC16(dB1[0], Bsrc1);
    CP_COMMIT();

    for (int kt = 0; kt < NHT; kt++) {
        const int buf = kt & 1;
        if (kt + 1 < NHT) {
            const int nb = buf ^ 1;
            const size_t oA = (size_t)(kt + 1) * stepA;
            const size_t oB = (size_t)(kt + 1) * stepB;
            CP_ASYNC16(dA0[nb], Asrc0 + oA);
            CP_ASYNC16(dA1[nb], Asrc1 + oA);
            CP_ASYNC16(dB0[nb], Bsrc0 + oB);
            CP_ASYNC16(dB1[nb], Bsrc1 + oB);
            CP_COMMIT();
            CP_WAIT(1);
        } else {
            CP_WAIT(0);
        }
        __syncthreads();

#pragma unroll
        for (int kk = 0; kk < BK; kk++) {
            float a[8], b[8];
            float4 a0 = *(const float4*)&As[buf][kk][ty * 8];
            float4 a1 = *(const float4*)&As[buf][kk][ty * 8 + 4];
            float4 b0 = *(const float4*)&Bs[buf][kk][tx * 8];
            float4 b1 = *(const float4*)&Bs[buf][kk][tx * 8 + 4];
            a[0]=a0.x; a[1]=a0.y; a[2]=a0.z; a[3]=a0.w;
            a[4]=a1.x; a[5]=a1.y; a[6]=a1.z; a[7]=a1.w;
            b[0]=b0.x; b[1]=b0.y; b[2]=b0.z; b[3]=b0.w;
            b[4]=b1.x; b[5]=b1.y; b[6]=b1.z; b[7]=b1.w;
#pragma unroll
            for (int i = 0; i < 8; i++)
#pragma unroll
                for (int j = 0; j < 8; j++)
                    acc[i][j] = fmaf(a[i], b[j], acc[i][j]);
        }
        __syncthreads();
    }

#pragma unroll
    for (int i = 0; i < 8; i++) {
        size_t base = (size_t)(m0 + ty * 8 + i) * N_DIM + n0 + tx * 8;
        *(float4*)&yout[base]     = make_float4(acc[i][0], acc[i][1], acc[i][2], acc[i][3]);
        *(float4*)&yout[base + 4] = make_float4(acc[i][4], acc[i][5], acc[i][6], acc[i][7]);
    }
}

// ---------------------------------------------------------------------------
// Encode (s0 + s1) -> 32 bit pulses (MSB first). One thread per 4 bits.
// The single fp32 add here IS the reference's split-K fold (same rounding).
// ---------------------------------------------------------------------------
__global__ void __launch_bounds__(256) encode_kernel(
    const float* __restrict__ y0, const float* __restrict__ y1,
    float4* __restrict__ out, int n4)
{
    int i = blockIdx.x * blockDim.x + threadIdx.x;
    if (i >= n4) return;
    int e = i >> 3;
    int g = i & 7;
    unsigned bits = __float_as_uint(__ldg(&y0[e]) + __ldg(&y1[e]));
    int sh = 31 - g * 4;
    float4 o;
    o.x = (float)((bits >> sh)       & 1u);
    o.y = (float)((bits >> (sh - 1)) & 1u);
    o.z = (float)((bits >> (sh - 2)) & 1u);
    o.w = (float)((bits >> (sh - 3)) & 1u);
    __stcs(&out[i], o);
}

// ---------------------------------------------------------------------------
extern "C" void kernel_launch(void* const* d_in, const int* in_sizes, int n_in,
                              void* d_out, int out_size)
{
    const float4* x = (const float4*)d_in[0];   // [8,256,1024,8]
    const float4* w = (const float4*)d_in[1];   // [1024,1024,8]

    float* xf; cudaGetSymbolAddress((void**)&xf, g_xf);
    float* wf; cudaGetSymbolAddress((void**)&wf, g_wf);
    float* y0; cudaGetSymbolAddress((void**)&y0, g_y0);
    float* y1; cudaGetSymbolAddress((void**)&y1, g_y1);

    dim3 dgx(K_DIM / 32, M_DIM / 32);   // (32, 64)
    decode_t_kernel<<<dgx, 256>>>(x, xf, M_DIM);
    dim3 dgw(K_DIM / 32, N_DIM / 32);   // (32, 32)
    decode_t_kernel<<<dgw, 256>>>(w, wf, N_DIM);

    dim3 ggrid(N_DIM / BN, M_DIM / BM, 2);   // (8, 16, 2) = 256 CTAs
    gemm_kernel<<<ggrid, 256>>>();

    const int n4 = M_DIM * N_DIM * 8;
    encode_kernel<<<(n4 + 255) / 256, 256>>>(y0, y1, (float4*)d_out, n4);
}